// round 8
// baseline (speedup 1.0000x reference)
#include <cuda_runtime.h>
#include <cuda_fp16.h>
#include <cstdint>

// ---------------------------------------------------------------------------
// AdaConv2d (sm_103, legacy mma.sync path):
//   K1 stats -> prepack (fp16 weights [tap][oc][ci]) -> K2 instancenorm +
//   adaptive grouped conv (fp16 y, NHWC reflect-pre-padded) -> halo ->
//   K3 fp16 implicit-GEMM final 3x3 conv.
// R8: fat CTA (256 oc x 128 px, 512 thr), CCH=128 -> 18 iters, B traffic
//     halved, stride-256 smem swizzle.
// ---------------------------------------------------------------------------

constexpr int B   = 8;
constexpr int C   = 256;
constexpr int H   = 128;
constexpr int W   = 128;
constexpr int G   = 32;
constexpr int CPG = 8;
constexpr int OUT = 256;
constexpr int HW  = H * W;
constexpr float EPS = 1e-5f;

constexpr int HP = H + 2;
constexpr int WP = W + 2;

constexpr int CCH = 128;     // ci per smem stage

// Device scratch
static __device__ float g_mean[B * C];
static __device__ float g_rsig[B * C];
static __device__ __half g_yh[(size_t)B * HP * WP * C];   // NHWC padded, fp16
static __device__ __half g_wh[9 * OUT * C];               // [tap][oc][ci] fp16

__device__ __forceinline__ int reflect_idx(int v, int n) {
    v = v < 0 ? -v : v;
    v = v >= n ? 2 * n - 2 - v : v;
    return v;
}

#define SWZ128(off) ((off) ^ (((off) >> 3) & 0x70))
// stride-256 rows: XOR row low-3-bits (off bits[10:8]) into 16B-chunk bits[6:4]
#define SWZ256(off) ((off) ^ (((off) >> 4) & 0x70))

__device__ __forceinline__ uint32_t smem_u32(const void* p) {
    uint32_t a;
    asm("{ .reg .u64 t; cvta.to.shared.u64 t, %1; cvt.u32.u64 %0, t; }"
        : "=r"(a) : "l"(p));
    return a;
}
__device__ __forceinline__ void cpa16(uint32_t dst, const void* src) {
    asm volatile("cp.async.cg.shared.global [%0], [%1], 16;"
                 :: "r"(dst), "l"(src));
}
#define CP_COMMIT() asm volatile("cp.async.commit_group;" ::: "memory")
#define CP_WAIT0()  asm volatile("cp.async.wait_group 0;" ::: "memory")

__device__ __forceinline__ void ldmx4(uint32_t* r, uint32_t addr) {
    asm volatile("ldmatrix.sync.aligned.m8n8.x4.shared.b16 {%0,%1,%2,%3}, [%4];"
                 : "=r"(r[0]), "=r"(r[1]), "=r"(r[2]), "=r"(r[3]) : "r"(addr));
}
__device__ __forceinline__ void mma16816(float* d, const uint32_t* a,
                                         const uint32_t* b) {
    asm volatile(
        "mma.sync.aligned.m16n8k16.row.col.f32.f16.f16.f32 "
        "{%0,%1,%2,%3},{%4,%5,%6,%7},{%8,%9},{%0,%1,%2,%3};"
        : "+f"(d[0]), "+f"(d[1]), "+f"(d[2]), "+f"(d[3])
        : "r"(a[0]), "r"(a[1]), "r"(a[2]), "r"(a[3]), "r"(b[0]), "r"(b[1]));
}

// ---------------------------------------------------------------------------
// K1: per-(b,c) mean / rsqrt(var+eps)
// ---------------------------------------------------------------------------
__global__ void stats_kernel(const float* __restrict__ x) {
    int bc = blockIdx.x;
    const float4* xp = reinterpret_cast<const float4*>(x + (size_t)bc * HW);
    float s = 0.f, ss = 0.f;
    #pragma unroll 4
    for (int i = threadIdx.x; i < HW / 4; i += 256) {
        float4 v = xp[i];
        s  += (v.x + v.y) + (v.z + v.w);
        ss += v.x * v.x + v.y * v.y + v.z * v.z + v.w * v.w;
    }
    #pragma unroll
    for (int o = 16; o; o >>= 1) {
        s  += __shfl_down_sync(0xFFFFFFFFu, s, o);
        ss += __shfl_down_sync(0xFFFFFFFFu, ss, o);
    }
    __shared__ float sh_s[8], sh_ss[8];
    int wid = threadIdx.x >> 5, lid = threadIdx.x & 31;
    if (lid == 0) { sh_s[wid] = s; sh_ss[wid] = ss; }
    __syncthreads();
    if (threadIdx.x == 0) {
        float ts = 0.f, tss = 0.f;
        #pragma unroll
        for (int i = 0; i < 8; i++) { ts += sh_s[i]; tss += sh_ss[i]; }
        float m   = ts * (1.f / HW);
        float var = tss * (1.f / HW) - m * m;
        g_mean[bc] = m;
        g_rsig[bc] = rsqrtf(var + EPS);
    }
}

// ---------------------------------------------------------------------------
// Weight prepack: conv_w [OUT][C][3][3] fp32 -> [tap][oc][ci] fp16
// ---------------------------------------------------------------------------
__global__ void prepack_kernel(const float* __restrict__ cw) {
    int idx = blockIdx.x * 256 + threadIdx.x;
    int tap = idx >> 16;
    int r   = idx & 0xFFFF;
    int oc  = r >> 8, ci = r & 255;
    g_wh[idx] = __float2half_rn(cw[(oc * C + ci) * 9 + tap]);
}

// ---------------------------------------------------------------------------
// K2: normalize + adaptive grouped 3x3 + 1x1 + bias -> fp16 NHWC padded
// ---------------------------------------------------------------------------
constexpr int T2W = 32, T2H = 16;

__global__ void ada_kernel(const float* __restrict__ x,
                           const float* __restrict__ ws,
                           const float* __restrict__ wp,
                           const float* __restrict__ bias) {
    __shared__ float s_in[CPG][T2H + 2][35];
    __shared__ float s_weff[CPG][CPG][9];
    __shared__ float s_wp[CPG][CPG];

    int bg = blockIdx.z;
    int b = bg / G, g = bg % G;
    int x0 = blockIdx.x * T2W, y0 = blockIdx.y * T2H;
    int tid = threadIdx.x;

    if (tid < CPG * CPG) {
        int o = tid >> 3, i = tid & 7;
        s_wp[o][i] = wp[(b * C + g * CPG + o) * CPG + i];
    }
    __syncthreads();

    for (int t = tid; t < CPG * CPG * 9; t += 256) {
        int o = t / 72, r = t % 72, j = r / 9, k = r % 9;
        float acc = 0.f;
        #pragma unroll
        for (int i = 0; i < CPG; i++)
            acc += s_wp[o][i] * ws[((b * C + g * CPG + i) * CPG + j) * 9 + k];
        s_weff[o][j][k] = acc;
    }

    for (int e = tid; e < CPG * (T2H + 2) * 34; e += 256) {
        int j   = e / ((T2H + 2) * 34);
        int r   = (e / 34) % (T2H + 2);
        int col = e % 34;
        int gy = reflect_idx(y0 + r - 1, H);
        int gx = reflect_idx(x0 + col - 1, W);
        int cg = b * C + g * CPG + j;
        s_in[j][r][col] = (x[(size_t)cg * HW + gy * W + gx] - g_mean[cg]) * g_rsig[cg];
    }
    __syncthreads();

    int px = (tid & 15) * 2;
    int py = tid >> 4;
    float acc[CPG][2];
    #pragma unroll
    for (int o = 0; o < CPG; o++) { acc[o][0] = 0.f; acc[o][1] = 0.f; }

    #pragma unroll
    for (int j = 0; j < CPG; j++) {
        #pragma unroll
        for (int ky = 0; ky < 3; ky++) {
            float i0 = s_in[j][py + ky][px + 0];
            float i1 = s_in[j][py + ky][px + 1];
            float i2 = s_in[j][py + ky][px + 2];
            float i3 = s_in[j][py + ky][px + 3];
            #pragma unroll
            for (int o = 0; o < CPG; o++) {
                float w0 = s_weff[o][j][ky * 3 + 0];
                float w1 = s_weff[o][j][ky * 3 + 1];
                float w2 = s_weff[o][j][ky * 3 + 2];
                acc[o][0] += w0 * i0 + w1 * i1 + w2 * i2;
                acc[o][1] += w0 * i1 + w1 * i2 + w2 * i3;
            }
        }
    }

    union U16 { __half h[8]; uint4 u; };
    U16 u0, u1;
    #pragma unroll
    for (int o = 0; o < CPG; o++) {
        float bz = bias[b * C + g * CPG + o];
        u0.h[o] = __float2half_rn(acc[o][0] + bz);
        u1.h[o] = __float2half_rn(acc[o][1] + bz);
    }
    size_t pbase = ((size_t)(b * HP + (y0 + py + 1)) * WP + (x0 + px + 1)) * C + g * CPG;
    *reinterpret_cast<uint4*>(g_yh + pbase)     = u0.u;
    *reinterpret_cast<uint4*>(g_yh + pbase + C) = u1.u;
}

// ---------------------------------------------------------------------------
// Halo fill (reflect) for the padded NHWC plane
// ---------------------------------------------------------------------------
__global__ void halo_kernel() {
    int e = blockIdx.x;      // 0..515
    int b = blockIdx.y;
    int py, px;
    if (e < 130)       { py = 0;            px = e; }
    else if (e < 260)  { py = 129;          px = e - 130; }
    else if (e < 388)  { py = e - 260 + 1;  px = 0; }
    else               { py = e - 388 + 1;  px = 129; }
    int sy = reflect_idx(py - 1, H) + 1;
    int sx = reflect_idx(px - 1, W) + 1;
    size_t dst = ((size_t)(b * HP + py) * WP + px) * C + threadIdx.x;
    size_t src = ((size_t)(b * HP + sy) * WP + sx) * C + threadIdx.x;
    g_yh[dst] = g_yh[src];
}

// ---------------------------------------------------------------------------
// K3: fp16 implicit-GEMM final conv, cp.async pipelined, fat CTA.
// CTA: 256 oc x 128 px (one row), 512 threads, 16 warps (4M x 4N),
// warp tile 64x32. CCH=128 -> 18 iterations (2 ci-chunks x 9 taps).
// Smem rows are 256B (128 ci fp16) with stride-256 swizzle.
// A double buffer 2x64KB + B double buffer 2x32.5KB = 193KB.
// ---------------------------------------------------------------------------
constexpr int A_BUF  = 256 * 256;                // 65536 (256 oc x 256B)
constexpr int OFF_A  = 0;                        // 2 buffers -> 131072
constexpr int B_BUF  = 130 * 256;                // 33280
constexpr int OFF_B  = 131072;                   // 2 buffers -> +66560
constexpr int SMEM_K3 = OFF_B + 2 * B_BUF;       // 197632

__global__ __launch_bounds__(512, 1)
void final_mma_kernel(const float* __restrict__ cb, float* __restrict__ out) {
    extern __shared__ char sb[];
    uint32_t su = smem_u32(sb);
    int tid  = threadIdx.x;
    int warp = tid >> 5, lane = tid & 31;
    int wm = warp >> 2;          // 0..3  -> oc base wm*64
    int wn = warp & 3;           // 0..3  -> px base wn*32

    int y0 = blockIdx.x;         // output row
    int b  = blockIdx.y;

    auto issue_A = [&](int tap, int c0, uint32_t abase) {
        #pragma unroll
        for (int q = 0; q < 8; q++) {
            int e = tid + q * 512;            // 4096 chunks: 256 rows x 16
            int r = e >> 4, j = e & 15;
            size_t gi = ((size_t)(tap * OUT + r)) * C + c0 + j * 8;
            cpa16(abase + SWZ256((uint32_t)(r * 256 + j * 16)), g_wh + gi);
        }
    };
    auto issue_B = [&](int c0, int dyi, uint32_t bbase) {
        for (int e = tid; e < 130 * 16; e += 512) {
            int r = e >> 4, j = e & 15;
            size_t gi = ((size_t)(b * HP + y0 + dyi) * WP + r) * C + c0 + j * 8;
            cpa16(bbase + SWZ256((uint32_t)(r * 256 + j * 16)), g_yh + gi);
        }
    };

    float acc[4][4][4];
    #pragma unroll
    for (int mi = 0; mi < 4; mi++)
        #pragma unroll
        for (int ni = 0; ni < 4; ni++)
            #pragma unroll
            for (int q = 0; q < 4; q++)
                acc[mi][ni][q] = 0.f;

    // ldmatrix lane address components
    uint32_t a_row = (uint32_t)(wm * 64 + (lane & 15));
    uint32_t a_kh  = (uint32_t)(lane >> 4) * 16;
    uint32_t b_row = (uint32_t)(wn * 32 + (lane & 7) + ((lane >> 4) << 3));
    uint32_t b_kh  = (uint32_t)((lane >> 3) & 1) * 16;

    // prologue: A(it=0) + B(group 0)
    issue_A(0, 0, su + OFF_A);
    issue_B(0, 0, su + OFF_B);
    CP_COMMIT();

    for (int it = 0; it < 18; it++) {
        int gi  = it / 3;                     // group = c0i*3 + dy (0..5)
        int dxi = it % 3;
        uint32_t abase = su + OFF_A + (it & 1) * A_BUF;
        uint32_t bbase = su + OFF_B + (gi & 1) * B_BUF;

        CP_WAIT0();
        __syncthreads();

        // prefetch next A every iter; next-group B at first iter of group
        if (it + 1 < 18) {
            int nit = it + 1;
            issue_A(nit % 9, (nit / 9) * CCH, su + OFF_A + (nit & 1) * A_BUF);
        }
        if (dxi == 0 && gi + 1 < 6) {
            int ng = gi + 1;
            issue_B((ng / 3) * CCH, ng % 3, su + OFF_B + (ng & 1) * B_BUF);
        }
        CP_COMMIT();

        // ---- compute: 8 k-steps over 128 ci
        #pragma unroll
        for (int ks = 0; ks < 8; ks++) {
            uint32_t kb = (uint32_t)ks * 32;
            uint32_t aF[4][4], bF[2][4];
            #pragma unroll
            for (int mi = 0; mi < 4; mi++) {
                uint32_t off = SWZ256((a_row + mi * 16) * 256 + kb + a_kh);
                ldmx4(aF[mi], abase + off);
            }
            #pragma unroll
            for (int nh = 0; nh < 2; nh++) {
                uint32_t off = SWZ256((b_row + nh * 16 + dxi) * 256 + kb + b_kh);
                ldmx4(bF[nh], bbase + off);
            }
            #pragma unroll
            for (int mi = 0; mi < 4; mi++)
                #pragma unroll
                for (int ni = 0; ni < 4; ni++)
                    mma16816(acc[mi][ni], aF[mi], &bF[ni >> 1][(ni & 1) * 2]);
        }
    }

    // Epilogue: +bias, direct float2 stores
    int row0 = lane >> 2;
    int col2 = (lane & 3) * 2;
    #pragma unroll
    for (int mi = 0; mi < 4; mi++) {
        int oc = wm * 64 + mi * 16 + row0;
        float bz0 = cb[oc];
        float bz1 = cb[oc + 8];
        size_t base0 = (((size_t)(b * OUT + oc))     * H + y0) * W;
        size_t base1 = (((size_t)(b * OUT + oc + 8)) * H + y0) * W;
        #pragma unroll
        for (int ni = 0; ni < 4; ni++) {
            int px = wn * 32 + ni * 8 + col2;
            float2 v0 = { acc[mi][ni][0] + bz0, acc[mi][ni][1] + bz0 };
            float2 v1 = { acc[mi][ni][2] + bz1, acc[mi][ni][3] + bz1 };
            *reinterpret_cast<float2*>(out + base0 + px) = v0;
            *reinterpret_cast<float2*>(out + base1 + px) = v1;
        }
    }
}

// ---------------------------------------------------------------------------
extern "C" void kernel_launch(void* const* d_in, const int* in_sizes, int n_in,
                              void* d_out, int out_size) {
    const float* x    = (const float*)d_in[0];
    const float* ws   = (const float*)d_in[1];
    const float* wp   = (const float*)d_in[2];
    const float* bias = (const float*)d_in[3];
    const float* cw   = (const float*)d_in[4];
    const float* cb   = (const float*)d_in[5];
    float* out = (float*)d_out;

    cudaFuncSetAttribute(final_mma_kernel,
                         cudaFuncAttributeMaxDynamicSharedMemorySize, SMEM_K3);

    stats_kernel<<<B * C, 256>>>(x);
    prepack_kernel<<<9 * OUT * C / 256, 256>>>(cw);
    ada_kernel<<<dim3(W / T2W, H / T2H, B * G), 256>>>(x, ws, wp, bias);
    halo_kernel<<<dim3(516, B), 256>>>();
    final_mma_kernel<<<dim3(H, B), 512, SMEM_K3>>>(cb, out);
}

// round 9
// speedup vs baseline: 1.0843x; 1.0843x over previous
#include <cuda_runtime.h>
#include <cuda_fp16.h>
#include <cstdint>

// ---------------------------------------------------------------------------
// AdaConv2d (sm_103, legacy mma.sync path):
//   K1 stats -> prepack (fp16 weights) -> K2 instancenorm + adaptive grouped
//   conv (fp16 y, NHWC reflect-pre-padded) -> halo -> K3 fp16 implicit-GEMM.
// R9: ada_kernel rewritten — 8 px/thread, packed fma.rn.f32x2, broadcast
//     weight LDS.64, conflict-free stride-35 smem. K3 = best-known R7 config.
// ---------------------------------------------------------------------------

constexpr int B   = 8;
constexpr int C   = 256;
constexpr int H   = 128;
constexpr int W   = 128;
constexpr int G   = 32;
constexpr int CPG = 8;
constexpr int OUT = 256;
constexpr int HW  = H * W;
constexpr float EPS = 1e-5f;

constexpr int HP = H + 2;
constexpr int WP = W + 2;

constexpr int MTILE = 128;   // oc per CTA (K3)
constexpr int CCH   = 64;    // ci per smem stage (K3)

typedef unsigned long long ull;

// Device scratch
static __device__ float g_mean[B * C];
static __device__ float g_rsig[B * C];
static __device__ __half g_yh[(size_t)B * HP * WP * C];   // NHWC padded, fp16
static __device__ __half g_wh[9 * OUT * C];               // [tap][oc][ci] fp16

__device__ __forceinline__ int reflect_idx(int v, int n) {
    v = v < 0 ? -v : v;
    v = v >= n ? 2 * n - 2 - v : v;
    return v;
}

#define SWZ128(off) ((off) ^ (((off) >> 3) & 0x70))

__device__ __forceinline__ uint32_t smem_u32(const void* p) {
    uint32_t a;
    asm("{ .reg .u64 t; cvta.to.shared.u64 t, %1; cvt.u32.u64 %0, t; }"
        : "=r"(a) : "l"(p));
    return a;
}
__device__ __forceinline__ void cpa16(uint32_t dst, const void* src) {
    asm volatile("cp.async.cg.shared.global [%0], [%1], 16;"
                 :: "r"(dst), "l"(src));
}
#define CP_COMMIT() asm volatile("cp.async.commit_group;" ::: "memory")
#define CP_WAIT0()  asm volatile("cp.async.wait_group 0;" ::: "memory")

__device__ __forceinline__ void ldmx4(uint32_t* r, uint32_t addr) {
    asm volatile("ldmatrix.sync.aligned.m8n8.x4.shared.b16 {%0,%1,%2,%3}, [%4];"
                 : "=r"(r[0]), "=r"(r[1]), "=r"(r[2]), "=r"(r[3]) : "r"(addr));
}
__device__ __forceinline__ void mma16816(float* d, const uint32_t* a,
                                         const uint32_t* b) {
    asm volatile(
        "mma.sync.aligned.m16n8k16.row.col.f32.f16.f16.f32 "
        "{%0,%1,%2,%3},{%4,%5,%6,%7},{%8,%9},{%0,%1,%2,%3};"
        : "+f"(d[0]), "+f"(d[1]), "+f"(d[2]), "+f"(d[3])
        : "r"(a[0]), "r"(a[1]), "r"(a[2]), "r"(a[3]), "r"(b[0]), "r"(b[1]));
}

// packed f32x2 helpers (Blackwell base ISA, sm_100+)
__device__ __forceinline__ ull pack2(float lo, float hi) {
    ull d;
    asm("mov.b64 %0, {%1, %2};" : "=l"(d) : "f"(lo), "f"(hi));
    return d;
}
__device__ __forceinline__ ull fma2(ull a, ull b, ull c) {
    ull d;
    asm("fma.rn.f32x2 %0, %1, %2, %3;" : "=l"(d) : "l"(a), "l"(b), "l"(c));
    return d;
}
__device__ __forceinline__ float2 unpack2(ull v) {
    float2 r;
    asm("mov.b64 {%0, %1}, %2;" : "=f"(r.x), "=f"(r.y) : "l"(v));
    return r;
}

// ---------------------------------------------------------------------------
// K1: per-(b,c) mean / rsqrt(var+eps)
// ---------------------------------------------------------------------------
__global__ void stats_kernel(const float* __restrict__ x) {
    int bc = blockIdx.x;
    const float4* xp = reinterpret_cast<const float4*>(x + (size_t)bc * HW);
    float s = 0.f, ss = 0.f;
    #pragma unroll 4
    for (int i = threadIdx.x; i < HW / 4; i += 256) {
        float4 v = xp[i];
        s  += (v.x + v.y) + (v.z + v.w);
        ss += v.x * v.x + v.y * v.y + v.z * v.z + v.w * v.w;
    }
    #pragma unroll
    for (int o = 16; o; o >>= 1) {
        s  += __shfl_down_sync(0xFFFFFFFFu, s, o);
        ss += __shfl_down_sync(0xFFFFFFFFu, ss, o);
    }
    __shared__ float sh_s[8], sh_ss[8];
    int wid = threadIdx.x >> 5, lid = threadIdx.x & 31;
    if (lid == 0) { sh_s[wid] = s; sh_ss[wid] = ss; }
    __syncthreads();
    if (threadIdx.x == 0) {
        float ts = 0.f, tss = 0.f;
        #pragma unroll
        for (int i = 0; i < 8; i++) { ts += sh_s[i]; tss += sh_ss[i]; }
        float m   = ts * (1.f / HW);
        float var = tss * (1.f / HW) - m * m;
        g_mean[bc] = m;
        g_rsig[bc] = rsqrtf(var + EPS);
    }
}

// ---------------------------------------------------------------------------
// Weight prepack: conv_w [OUT][C][3][3] fp32 -> [tap][oc][ci] fp16
// ---------------------------------------------------------------------------
__global__ void prepack_kernel(const float* __restrict__ cw) {
    int idx = blockIdx.x * 256 + threadIdx.x;
    int tap = idx >> 16;
    int r   = idx & 0xFFFF;
    int oc  = r >> 8, ci = r & 255;
    g_wh[idx] = __float2half_rn(cw[(oc * C + ci) * 9 + tap]);
}

// ---------------------------------------------------------------------------
// K2 (R9): normalize + adaptive grouped 3x3 + 1x1 + bias -> fp16 NHWC padded.
// 32x32 tile, 128 threads, 8 px/thread, packed f32x2 fma.
// ---------------------------------------------------------------------------
constexpr int T2W = 32, T2H = 32;

__global__ __launch_bounds__(128, 4)
void ada_kernel(const float* __restrict__ x,
                const float* __restrict__ ws,
                const float* __restrict__ wp,
                const float* __restrict__ bias) {
    __shared__ float s_in[CPG][T2H + 2][35];   // stride 35: conflict-free
    __shared__ ull   s_w2[CPG][CPG][9];        // [o][j][k], weight duplicated
    __shared__ float s_wp[CPG][CPG];

    int bg = blockIdx.z;
    int b = bg >> 5, g = bg & 31;
    int x0 = blockIdx.x * T2W, y0 = blockIdx.y * T2H;
    int tid = threadIdx.x;

    if (tid < CPG * CPG) {
        int o = tid >> 3, i = tid & 7;
        s_wp[o][i] = wp[(b * C + g * CPG + o) * CPG + i];
    }
    __syncthreads();

    // fold 1x1 into spatial weights, store duplicated (w,w) pairs
    for (int t = tid; t < CPG * CPG * 9; t += 128) {
        int o = t / 72, r = t % 72, j = r / 9, k = r % 9;
        float acc = 0.f;
        #pragma unroll
        for (int i = 0; i < CPG; i++)
            acc += s_wp[o][i] * ws[((b * C + g * CPG + i) * CPG + j) * 9 + k];
        s_w2[o][j][k] = pack2(acc, acc);
    }

    // normalized input tile with reflect halo: 8 ch x 34 x 34
    for (int e = tid; e < CPG * (T2H + 2) * 34; e += 128) {
        int j   = e / ((T2H + 2) * 34);
        int r   = (e / 34) % (T2H + 2);
        int col = e % 34;
        int gy = reflect_idx(y0 + r - 1, H);
        int gx = reflect_idx(x0 + col - 1, W);
        int cg = b * C + g * CPG + j;
        s_in[j][r][col] = (x[(size_t)cg * HW + gy * W + gx] - g_mean[cg]) * g_rsig[cg];
    }
    __syncthreads();

    int px = (tid & 3) * 8;     // 0,8,16,24
    int py = tid >> 2;          // 0..31

    ull acc[CPG][4];
    #pragma unroll
    for (int o = 0; o < CPG; o++)
        #pragma unroll
        for (int q = 0; q < 4; q++)
            acc[o][q] = 0ull;

    #pragma unroll
    for (int j = 0; j < CPG; j++) {
        #pragma unroll
        for (int ky = 0; ky < 3; ky++) {
            const float* row = &s_in[j][py + ky][px];
            float in[10];
            #pragma unroll
            for (int k = 0; k < 10; k++) in[k] = row[k];
            ull P0[4], P1[4], P2[4];
            #pragma unroll
            for (int q = 0; q < 4; q++) {
                P0[q] = pack2(in[2 * q],     in[2 * q + 1]);
                P1[q] = pack2(in[2 * q + 1], in[2 * q + 2]);
            }
            P2[0] = P0[1]; P2[1] = P0[2]; P2[2] = P0[3];
            P2[3] = pack2(in[8], in[9]);
            #pragma unroll
            for (int o = 0; o < CPG; o++) {
                ull w0 = s_w2[o][j][ky * 3 + 0];
                ull w1 = s_w2[o][j][ky * 3 + 1];
                ull w2 = s_w2[o][j][ky * 3 + 2];
                #pragma unroll
                for (int q = 0; q < 4; q++) {
                    acc[o][q] = fma2(w0, P0[q], acc[o][q]);
                    acc[o][q] = fma2(w1, P1[q], acc[o][q]);
                    acc[o][q] = fma2(w2, P2[q], acc[o][q]);
                }
            }
        }
    }

    float bz[CPG];
    #pragma unroll
    for (int o = 0; o < CPG; o++) bz[o] = bias[b * C + g * CPG + o];

    union U16 { __half h[8]; uint4 u; };
    size_t pbase = ((size_t)(b * HP + (y0 + py + 1)) * WP + (x0 + px + 1)) * C
                   + g * CPG;
    #pragma unroll
    for (int q = 0; q < 4; q++) {
        U16 ua, ub;
        #pragma unroll
        for (int o = 0; o < CPG; o++) {
            float2 v = unpack2(acc[o][q]);
            ua.h[o] = __float2half_rn(v.x + bz[o]);
            ub.h[o] = __float2half_rn(v.y + bz[o]);
        }
        *reinterpret_cast<uint4*>(g_yh + pbase + (2 * q)     * C) = ua.u;
        *reinterpret_cast<uint4*>(g_yh + pbase + (2 * q + 1) * C) = ub.u;
    }
}

// ---------------------------------------------------------------------------
// Halo fill (reflect) for the padded NHWC plane
// ---------------------------------------------------------------------------
__global__ void halo_kernel() {
    int e = blockIdx.x;      // 0..515
    int b = blockIdx.y;
    int py, px;
    if (e < 130)       { py = 0;            px = e; }
    else if (e < 260)  { py = 129;          px = e - 130; }
    else if (e < 388)  { py = e - 260 + 1;  px = 0; }
    else               { py = e - 388 + 1;  px = 129; }
    int sy = reflect_idx(py - 1, H) + 1;
    int sx = reflect_idx(px - 1, W) + 1;
    size_t dst = ((size_t)(b * HP + py) * WP + px) * C + threadIdx.x;
    size_t src = ((size_t)(b * HP + sy) * WP + sx) * C + threadIdx.x;
    g_yh[dst] = g_yh[src];
}

// ---------------------------------------------------------------------------
// K3: fp16 implicit-GEMM final conv (R7 best-known config).
// CTA: 128 oc x 128 px, 8 warps (2M x 4N), warp tile 64x32, CCH=64,
// A double buffer 2x16KB + B double buffer 2x16.6KB.
// ---------------------------------------------------------------------------
constexpr int A_BUF  = 16384;
constexpr int OFF_A  = 0;
constexpr int B_BUF  = 130 * 128;
constexpr int OFF_B  = 32768;
constexpr int SMEM_K3 = OFF_B + 2 * B_BUF;       // 66048

__global__ __launch_bounds__(256, 2)
void final_mma_kernel(const float* __restrict__ cb, float* __restrict__ out) {
    extern __shared__ char sb[];
    uint32_t su = smem_u32(sb);
    int tid  = threadIdx.x;
    int warp = tid >> 5, lane = tid & 31;
    int wm = warp >> 2;
    int wn = warp & 3;

    int y0  = blockIdx.x;
    int b   = blockIdx.y;
    int ocb = blockIdx.z;

    int a_r[4], a_j[4];
    uint32_t a_soff[4];
    #pragma unroll
    for (int q = 0; q < 4; q++) {
        int e = tid + q * 256;
        a_r[q] = e >> 3; a_j[q] = e & 7;
        a_soff[q] = SWZ128((uint32_t)(a_r[q] * 128 + a_j[q] * 16));
    }

    auto issue_A = [&](int tap, int c0, uint32_t abase) {
        #pragma unroll
        for (int q = 0; q < 4; q++) {
            size_t gi = ((size_t)(tap * OUT + ocb * MTILE + a_r[q])) * C
                        + c0 + a_j[q] * 8;
            cpa16(abase + a_soff[q], g_wh + gi);
        }
    };
    auto issue_B = [&](int c0, int dyi, uint32_t bbase) {
        for (int e = tid; e < 130 * 8; e += 256) {
            int r = e >> 3, j = e & 7;
            size_t gi = ((size_t)(b * HP + y0 + dyi) * WP + r) * C + c0 + j * 8;
            uint32_t off = SWZ128((uint32_t)(r * 128 + j * 16));
            cpa16(bbase + off, g_yh + gi);
        }
    };

    float acc[4][4][4];
    #pragma unroll
    for (int mi = 0; mi < 4; mi++)
        #pragma unroll
        for (int ni = 0; ni < 4; ni++)
            #pragma unroll
            for (int q = 0; q < 4; q++)
                acc[mi][ni][q] = 0.f;

    uint32_t a_row = (uint32_t)(wm * 64 + (lane & 15));
    uint32_t a_kh  = (uint32_t)(lane >> 4) * 16;
    uint32_t b_row = (uint32_t)(wn * 32 + (lane & 7) + ((lane >> 4) << 3));
    uint32_t b_kh  = (uint32_t)((lane >> 3) & 1) * 16;

    issue_A(0, 0, su + OFF_A);
    issue_B(0, 0, su + OFF_B);
    CP_COMMIT();

    for (int it = 0; it < 36; it++) {
        int gi  = it / 3;
        int dxi = it % 3;
        uint32_t abase = su + OFF_A + (it & 1) * A_BUF;
        uint32_t bbase = su + OFF_B + (gi & 1) * B_BUF;

        CP_WAIT0();
        __syncthreads();

        if (it + 1 < 36) {
            int nit = it + 1;
            issue_A(nit % 9, (nit / 9) * CCH, su + OFF_A + (nit & 1) * A_BUF);
        }
        if (dxi == 0 && gi + 1 < 12) {
            int ng = gi + 1;
            issue_B((ng / 3) * CCH, ng % 3, su + OFF_B + (ng & 1) * B_BUF);
        }
        CP_COMMIT();

        #pragma unroll
        for (int ks = 0; ks < 4; ks++) {
            uint32_t kb = (uint32_t)ks * 32;
            uint32_t aF[4][4], bF[2][4];
            #pragma unroll
            for (int mi = 0; mi < 4; mi++) {
                uint32_t off = SWZ128((a_row + mi * 16) * 128 + kb + a_kh);
                ldmx4(aF[mi], abase + off);
            }
            #pragma unroll
            for (int nh = 0; nh < 2; nh++) {
                uint32_t off = SWZ128((b_row + nh * 16 + dxi) * 128 + kb + b_kh);
                ldmx4(bF[nh], bbase + off);
            }
            #pragma unroll
            for (int mi = 0; mi < 4; mi++)
                #pragma unroll
                for (int ni = 0; ni < 4; ni++)
                    mma16816(acc[mi][ni], aF[mi], &bF[ni >> 1][(ni & 1) * 2]);
        }
    }

    int row0 = lane >> 2;
    int col2 = (lane & 3) * 2;
    #pragma unroll
    for (int mi = 0; mi < 4; mi++) {
        int oc = ocb * MTILE + wm * 64 + mi * 16 + row0;
        float bz0 = cb[oc];
        float bz1 = cb[oc + 8];
        size_t base0 = (((size_t)(b * OUT + oc))     * H + y0) * W;
        size_t base1 = (((size_t)(b * OUT + oc + 8)) * H + y0) * W;
        #pragma unroll
        for (int ni = 0; ni < 4; ni++) {
            int px = wn * 32 + ni * 8 + col2;
            float2 v0 = { acc[mi][ni][0] + bz0, acc[mi][ni][1] + bz0 };
            float2 v1 = { acc[mi][ni][2] + bz1, acc[mi][ni][3] + bz1 };
            *reinterpret_cast<float2*>(out + base0 + px) = v0;
            *reinterpret_cast<float2*>(out + base1 + px) = v1;
        }
    }
}

// ---------------------------------------------------------------------------
extern "C" void kernel_launch(void* const* d_in, const int* in_sizes, int n_in,
                              void* d_out, int out_size) {
    const float* x    = (const float*)d_in[0];
    const float* ws   = (const float*)d_in[1];
    const float* wp   = (const float*)d_in[2];
    const float* bias = (const float*)d_in[3];
    const float* cw   = (const float*)d_in[4];
    const float* cb   = (const float*)d_in[5];
    float* out = (float*)d_out;

    cudaFuncSetAttribute(final_mma_kernel,
                         cudaFuncAttributeMaxDynamicSharedMemorySize, SMEM_K3);

    stats_kernel<<<B * C, 256>>>(x);
    prepack_kernel<<<9 * OUT * C / 256, 256>>>(cw);
    ada_kernel<<<dim3(W / T2W, H / T2H, B * G), 128>>>(x, ws, wp, bias);
    halo_kernel<<<dim3(516, B), 256>>>();
    final_mma_kernel<<<dim3(H, B, OUT / MTILE), 256, SMEM_K3>>>(cb, out);
}